// round 4
// baseline (speedup 1.0000x reference)
#include <cuda_runtime.h>
#include <math.h>

#define N_NODES 50000
#define N_EDGES 800000
#define F       128
#define NG      128
#define NOUT    10
#define BN_EPS  1e-5f

// ---------------- scratch (device globals; no runtime allocs) ----------------
__device__ float g_deg_out[N_NODES];
__device__ float g_deg_in [N_NODES];
__device__ float g_iso[N_NODES];   // rsqrt(max(deg_out,1))
__device__ float g_isi[N_NODES];   // rsqrt(max(deg_in,1))
__device__ float g_h  [N_NODES * F];   // projected features (pre-scatter)
__device__ float g_agg[N_NODES * F];   // scatter-add accumulator
__device__ float g_x  [N_NODES * F];   // layer output
__device__ float g_mu  [F];
__device__ float g_istd[F];

// ---------------- degrees ----------------
__global__ void k_zero_deg() {
    int i = blockIdx.x * blockDim.x + threadIdx.x;
    if (i < N_NODES) { g_deg_out[i] = 0.f; g_deg_in[i] = 0.f; }
}

__global__ void k_deg(const int* __restrict__ src, const int* __restrict__ dst) {
    int e = blockIdx.x * blockDim.x + threadIdx.x;
    if (e < N_EDGES) {
        atomicAdd(&g_deg_out[src[e]], 1.f);
        atomicAdd(&g_deg_in [dst[e]], 1.f);
    }
}

__global__ void k_inv() {
    int i = blockIdx.x * blockDim.x + threadIdx.x;
    if (i < N_NODES) {
        g_iso[i] = rsqrtf(fmaxf(g_deg_out[i], 1.f));
        g_isi[i] = rsqrtf(fmaxf(g_deg_in [i], 1.f));
    }
}

// ---------------- GEMM: g_h[n][j] = sum_k (X[n][k]*iso[n]) * W[k][j] ----------------
// BM=64 rows per block, BN=128 (full), BK=16; 256 threads; each thread 8x4 outputs.
__global__ void k_gemm(const float* __restrict__ X0, const float* __restrict__ W,
                       int use_gx) {
    const float* X = use_gx ? (const float*)g_x : X0;
    __shared__ float As[16][64];
    __shared__ float Bs[16][F];

    int tid = threadIdx.x;
    int tx  = tid & 31;      // col group: cols tx*4 .. tx*4+3
    int ty  = tid >> 5;      // row group: rows ty*8 .. ty*8+7
    int row0 = blockIdx.x * 64;

    float acc[8][4];
#pragma unroll
    for (int i = 0; i < 8; i++)
#pragma unroll
        for (int j = 0; j < 4; j++) acc[i][j] = 0.f;

    for (int kt = 0; kt < F; kt += 16) {
        // load A tile (64x16), scaled by iso[row]
#pragma unroll
        for (int i = 0; i < 4; i++) {
            int e = tid + i * 256;
            int r = e >> 4, c = e & 15;
            int row = row0 + r;
            float v = 0.f;
            if (row < N_NODES) v = X[row * F + kt + c] * g_iso[row];
            As[c][r] = v;
        }
        // load B tile (16x128)
#pragma unroll
        for (int i = 0; i < 8; i++) {
            int e = tid + i * 256;
            int kr = e >> 7, c = e & 127;
            Bs[kr][c] = W[(kt + kr) * F + c];
        }
        __syncthreads();

#pragma unroll
        for (int k = 0; k < 16; k++) {
            float4 b = *(const float4*)&Bs[k][tx * 4];
#pragma unroll
            for (int i = 0; i < 8; i++) {
                float a = As[k][ty * 8 + i];
                acc[i][0] = fmaf(a, b.x, acc[i][0]);
                acc[i][1] = fmaf(a, b.y, acc[i][1]);
                acc[i][2] = fmaf(a, b.z, acc[i][2]);
                acc[i][3] = fmaf(a, b.w, acc[i][3]);
            }
        }
        __syncthreads();
    }

#pragma unroll
    for (int i = 0; i < 8; i++) {
        int row = row0 + ty * 8 + i;
        if (row < N_NODES) {
            float4 v = make_float4(acc[i][0], acc[i][1], acc[i][2], acc[i][3]);
            *(float4*)&g_h[row * F + tx * 4] = v;
        }
    }
}

// ---------------- zero the scatter accumulator ----------------
__global__ void k_zero_agg() {
    int t = blockIdx.x * blockDim.x + threadIdx.x;   // N_NODES*32 float4 slots
    if (t < N_NODES * 32) {
        *(float4*)&g_agg[t * 4] = make_float4(0.f, 0.f, 0.f, 0.f);
    }
}

// ---------------- edge scatter: agg[dst] += h[src]  (one warp per edge) ----------------
__global__ void k_scatter(const int* __restrict__ src, const int* __restrict__ dst) {
    int t = blockIdx.x * blockDim.x + threadIdx.x;
    int e = t >> 5, lane = t & 31;
    if (e < N_EDGES) {
        int s = src[e], d = dst[e];
        float4 v = *(const float4*)&g_h[s * F + lane * 4];
        float* o = &g_agg[d * F + lane * 4];
        atomicAdd(o + 0, v.x);
        atomicAdd(o + 1, v.y);
        atomicAdd(o + 2, v.z);
        atomicAdd(o + 3, v.w);
    }
}

// ---------------- finalize: g_x = relu(agg * isi + b) ----------------
__global__ void k_fin(const float* __restrict__ b) {
    int t = blockIdx.x * blockDim.x + threadIdx.x;
    if (t < N_NODES * 32) {
        int n = t >> 5, c = t & 31;
        float s = g_isi[n];
        float4 v = *(const float4*)&g_agg[n * F + c * 4];
        const float4 bb = *(const float4*)&b[c * 4];
        v.x = fmaxf(fmaf(v.x, s, bb.x), 0.f);
        v.y = fmaxf(fmaf(v.y, s, bb.y), 0.f);
        v.z = fmaxf(fmaf(v.z, s, bb.z), 0.f);
        v.w = fmaxf(fmaf(v.w, s, bb.w), 0.f);
        *(float4*)&g_x[n * F + c * 4] = v;
    }
}

// ---------------- sum-pool into d_out[0 : NG*F] ----------------
__global__ void k_pool(const int* __restrict__ gid, float* __restrict__ out) {
    int t = blockIdx.x * blockDim.x + threadIdx.x;
    if (t < N_NODES * 32) {
        int n = t >> 5, c = t & 31;
        int g = gid[n];
        float4 v = *(const float4*)&g_x[n * F + c * 4];
        float* o = &out[g * F + c * 4];
        atomicAdd(o + 0, v.x);
        atomicAdd(o + 1, v.y);
        atomicAdd(o + 2, v.z);
        atomicAdd(o + 3, v.w);
    }
}

// ---------------- batchnorm stats over graphs (axis 0) ----------------
__global__ void k_stats(const float* __restrict__ E) {
    int j = threadIdx.x;   // 128 threads, 1 block
    float s = 0.f, s2 = 0.f;
    for (int g = 0; g < NG; g++) {
        float v = E[g * F + j];
        s += v; s2 = fmaf(v, v, s2);
    }
    float mu = s * (1.f / NG);
    float var = s2 * (1.f / NG) - mu * mu;
    g_mu[j] = mu;
    g_istd[j] = rsqrtf(var + BN_EPS);
}

// ---------------- BN + MLP + log_softmax (one block per graph) ----------------
__global__ void k_mlp(const float* __restrict__ E,
                      const float* __restrict__ gamma, const float* __restrict__ beta,
                      const float* __restrict__ fc1w, const float* __restrict__ fc1b,
                      const float* __restrict__ fc2w, const float* __restrict__ fc2b,
                      float* __restrict__ out_logits) {
    int g = blockIdx.x, j = threadIdx.x;   // 128 threads
    __shared__ float bn[F];
    __shared__ float h[F];
    __shared__ float l[NOUT];
    __shared__ float lse;

    bn[j] = fmaf(gamma[j] * (E[g * F + j] - g_mu[j]), g_istd[j], beta[j]);
    __syncthreads();

    float acc = fc1b[j];
#pragma unroll 8
    for (int k = 0; k < F; k++) acc = fmaf(bn[k], fc1w[k * F + j], acc);
    h[j] = fmaxf(acc, 0.f);
    __syncthreads();

    if (j < NOUT) {
        float a = fc2b[j];
#pragma unroll 8
        for (int k = 0; k < F; k++) a = fmaf(h[k], fc2w[k * NOUT + j], a);
        l[j] = a;
    }
    __syncthreads();

    if (j == 0) {
        float m = -INFINITY;
        for (int o = 0; o < NOUT; o++) m = fmaxf(m, l[o]);
        float s = 0.f;
        for (int o = 0; o < NOUT; o++) s += expf(l[o] - m);
        lse = m + logf(s);
    }
    __syncthreads();

    if (j < NOUT) out_logits[g * NOUT + j] = l[j] - lse;
}

// ---------------- launch ----------------
extern "C" void kernel_launch(void* const* d_in, const int* in_sizes, int n_in,
                              void* d_out, int out_size) {
    const float* n_feat = (const float*)d_in[0];
    const int*   src    = (const int*)  d_in[1];
    const int*   dst    = (const int*)  d_in[2];
    const int*   gid    = (const int*)  d_in[3];
    const float* W1     = (const float*)d_in[4];
    const float* b1     = (const float*)d_in[5];
    const float* W2     = (const float*)d_in[6];
    const float* b2     = (const float*)d_in[7];
    const float* gamma  = (const float*)d_in[8];
    const float* beta   = (const float*)d_in[9];
    const float* fc1w   = (const float*)d_in[10];
    const float* fc1b   = (const float*)d_in[11];
    const float* fc2w   = (const float*)d_in[12];
    const float* fc2b   = (const float*)d_in[13];
    float* out = (float*)d_out;

    const int TB = 256;
    const int nodeBlocks  = (N_NODES + TB - 1) / TB;
    const int edgeBlocks  = (N_EDGES + TB - 1) / TB;
    const int gemmBlocks  = (N_NODES + 63) / 64;
    const int vec4Blocks  = (N_NODES * 32 + TB - 1) / TB;   // node*feature4 threads
    const int scatBlocks  = (N_EDGES * 32 + TB - 1) / TB;   // warp per edge

    // degrees + norms
    k_zero_deg<<<nodeBlocks, TB>>>();
    k_deg<<<edgeBlocks, TB>>>(src, dst);
    k_inv<<<nodeBlocks, TB>>>();

    // layer 1
    k_gemm<<<gemmBlocks, TB>>>(n_feat, W1, 0);
    k_zero_agg<<<vec4Blocks, TB>>>();
    k_scatter<<<scatBlocks, TB>>>(src, dst);
    k_fin<<<vec4Blocks, TB>>>(b1);

    // layer 2
    k_gemm<<<gemmBlocks, TB>>>(nullptr, W2, 1);
    k_zero_agg<<<vec4Blocks, TB>>>();
    k_scatter<<<scatBlocks, TB>>>(src, dst);
    k_fin<<<vec4Blocks, TB>>>(b2);

    // pooling into d_out embedding region (zero it first; d_out is poisoned)
    cudaMemsetAsync(out, 0, NG * F * sizeof(float), 0);
    k_pool<<<vec4Blocks, TB>>>(gid, out);

    // head
    k_stats<<<1, F>>>(out);
    k_mlp<<<NG, F>>>(out, gamma, beta, fc1w, fc1b, fc2w, fc2b, out + NG * F);
}

// round 5
// speedup vs baseline: 1.6859x; 1.6859x over previous
#include <cuda_runtime.h>
#include <math.h>

#define N_NODES 50000
#define N_EDGES 800000
#define F       128
#define NG      128
#define NOUT    10
#define BN_EPS  1e-5f

// ---------------- scratch (device globals; no runtime allocs) ----------------
__device__ float g_deg_out[N_NODES];
__device__ float g_deg_in [N_NODES];
__device__ float g_iso[N_NODES];   // rsqrt(max(deg_out,1))
__device__ float g_isi[N_NODES];   // rsqrt(max(deg_in,1))
__device__ float g_h  [N_NODES * F];   // projected features (pre-gather)
__device__ float g_x  [N_NODES * F];   // layer output
__device__ int   g_row_ptr[N_NODES + 1];
__device__ int   g_cursor [N_NODES];
__device__ int   g_csr_src[N_EDGES];
__device__ float g_mu  [F];
__device__ float g_istd[F];

// ---------------- degrees ----------------
__global__ void k_zero_deg() {
    int i = blockIdx.x * blockDim.x + threadIdx.x;
    if (i < N_NODES) { g_deg_out[i] = 0.f; g_deg_in[i] = 0.f; }
}

__global__ void k_deg(const int* __restrict__ src, const int* __restrict__ dst) {
    int e = blockIdx.x * blockDim.x + threadIdx.x;
    if (e < N_EDGES) {
        atomicAdd(&g_deg_out[src[e]], 1.f);
        atomicAdd(&g_deg_in [dst[e]], 1.f);
    }
}

__global__ void k_inv() {
    int i = blockIdx.x * blockDim.x + threadIdx.x;
    if (i < N_NODES) {
        g_iso[i] = rsqrtf(fmaxf(g_deg_out[i], 1.f));
        g_isi[i] = rsqrtf(fmaxf(g_deg_in [i], 1.f));
    }
}

// ---------------- exclusive scan of in-degrees -> row_ptr, cursor ----------------
// Single block, 1024 threads, chunked shuffle scan. 50k elements -> 49 iters.
__global__ void k_scan() {
    __shared__ int wsum[32];
    __shared__ int carry_s;
    int tid = threadIdx.x;
    if (tid == 0) carry_s = 0;
    __syncthreads();

    for (int base = 0; base < N_NODES; base += 1024) {
        int idx = base + tid;
        int v = (idx < N_NODES) ? (int)g_deg_in[idx] : 0;

        // inclusive warp scan
        int x = v;
#pragma unroll
        for (int o = 1; o < 32; o <<= 1) {
            int y = __shfl_up_sync(0xFFFFFFFFu, x, o);
            if ((tid & 31) >= o) x += y;
        }
        if ((tid & 31) == 31) wsum[tid >> 5] = x;
        __syncthreads();
        if (tid < 32) {
            int w = wsum[tid];
#pragma unroll
            for (int o = 1; o < 32; o <<= 1) {
                int y = __shfl_up_sync(0xFFFFFFFFu, w, o);
                if (tid >= o) w += y;
            }
            wsum[tid] = w;
        }
        __syncthreads();

        int warpoff = (tid >= 32) ? wsum[(tid >> 5) - 1] : 0;
        int incl = x + warpoff;
        int carry = carry_s;                 // read BEFORE update (sync below)
        if (idx < N_NODES) {
            int excl = carry + incl - v;
            g_row_ptr[idx] = excl;
            g_cursor [idx] = excl;
        }
        __syncthreads();
        if (tid == 1023) carry_s = carry + incl;
        __syncthreads();
    }
    if (tid == 0) g_row_ptr[N_NODES] = carry_s;
}

// ---------------- bucket edges by dst ----------------
__global__ void k_fill(const int* __restrict__ src, const int* __restrict__ dst) {
    int e = blockIdx.x * blockDim.x + threadIdx.x;
    if (e < N_EDGES) {
        int d = dst[e];
        int p = atomicAdd(&g_cursor[d], 1);
        g_csr_src[p] = src[e];
    }
}

// ---------------- GEMM: g_h[n][j] = sum_k (X[n][k]*iso[n]) * W[k][j] ----------------
__global__ void k_gemm(const float* __restrict__ X0, const float* __restrict__ W,
                       int use_gx) {
    const float* X = use_gx ? (const float*)g_x : X0;
    __shared__ float As[16][64];
    __shared__ float Bs[16][F];

    int tid = threadIdx.x;
    int tx  = tid & 31;
    int ty  = tid >> 5;
    int row0 = blockIdx.x * 64;

    float acc[8][4];
#pragma unroll
    for (int i = 0; i < 8; i++)
#pragma unroll
        for (int j = 0; j < 4; j++) acc[i][j] = 0.f;

    for (int kt = 0; kt < F; kt += 16) {
#pragma unroll
        for (int i = 0; i < 4; i++) {
            int e = tid + i * 256;
            int r = e >> 4, c = e & 15;
            int row = row0 + r;
            float v = 0.f;
            if (row < N_NODES) v = X[row * F + kt + c] * g_iso[row];
            As[c][r] = v;
        }
#pragma unroll
        for (int i = 0; i < 8; i++) {
            int e = tid + i * 256;
            int kr = e >> 7, c = e & 127;
            Bs[kr][c] = W[(kt + kr) * F + c];
        }
        __syncthreads();

#pragma unroll
        for (int k = 0; k < 16; k++) {
            float4 b = *(const float4*)&Bs[k][tx * 4];
#pragma unroll
            for (int i = 0; i < 8; i++) {
                float a = As[k][ty * 8 + i];
                acc[i][0] = fmaf(a, b.x, acc[i][0]);
                acc[i][1] = fmaf(a, b.y, acc[i][1]);
                acc[i][2] = fmaf(a, b.z, acc[i][2]);
                acc[i][3] = fmaf(a, b.w, acc[i][3]);
            }
        }
        __syncthreads();
    }

#pragma unroll
    for (int i = 0; i < 8; i++) {
        int row = row0 + ty * 8 + i;
        if (row < N_NODES) {
            float4 v = make_float4(acc[i][0], acc[i][1], acc[i][2], acc[i][3]);
            *(float4*)&g_h[row * F + tx * 4] = v;
        }
    }
}

// ---------------- CSR gather + fused epilogue: g_x = relu(sum(h[src]) * isi + b) ----------------
// One warp per node; lane covers 4 features (float4). Edge loop unrolled x4 for MLP.
__global__ void k_gather(const float* __restrict__ b) {
    int t = blockIdx.x * blockDim.x + threadIdx.x;
    int n = t >> 5, lane = t & 31;
    if (n >= N_NODES) return;

    int beg = g_row_ptr[n], end = g_row_ptr[n + 1];
    float4 acc = make_float4(0.f, 0.f, 0.f, 0.f);

    int i = beg;
    for (; i + 4 <= end; i += 4) {
        int s0 = g_csr_src[i + 0];
        int s1 = g_csr_src[i + 1];
        int s2 = g_csr_src[i + 2];
        int s3 = g_csr_src[i + 3];
        float4 v0 = *(const float4*)&g_h[s0 * F + lane * 4];
        float4 v1 = *(const float4*)&g_h[s1 * F + lane * 4];
        float4 v2 = *(const float4*)&g_h[s2 * F + lane * 4];
        float4 v3 = *(const float4*)&g_h[s3 * F + lane * 4];
        acc.x += (v0.x + v1.x) + (v2.x + v3.x);
        acc.y += (v0.y + v1.y) + (v2.y + v3.y);
        acc.z += (v0.z + v1.z) + (v2.z + v3.z);
        acc.w += (v0.w + v1.w) + (v2.w + v3.w);
    }
    for (; i < end; i++) {
        int s = g_csr_src[i];
        float4 v = *(const float4*)&g_h[s * F + lane * 4];
        acc.x += v.x; acc.y += v.y; acc.z += v.z; acc.w += v.w;
    }

    float si = g_isi[n];
    float4 bb = *(const float4*)&b[lane * 4];
    acc.x = fmaxf(fmaf(acc.x, si, bb.x), 0.f);
    acc.y = fmaxf(fmaf(acc.y, si, bb.y), 0.f);
    acc.z = fmaxf(fmaf(acc.z, si, bb.z), 0.f);
    acc.w = fmaxf(fmaf(acc.w, si, bb.w), 0.f);
    *(float4*)&g_x[n * F + lane * 4] = acc;
}

// ---------------- sum-pool exploiting sorted graph_ids ----------------
// One block per 512-node chunk, 128 threads (one per feature).
// Running register sum, flushed via atomic only on gid change / chunk end.
#define POOL_CHUNK 512
__global__ void k_pool(const int* __restrict__ gid, float* __restrict__ out) {
    int j = threadIdx.x;
    int n0 = blockIdx.x * POOL_CHUNK;
    int n1 = n0 + POOL_CHUNK;
    if (n1 > N_NODES) n1 = N_NODES;

    int curg = __ldg(&gid[n0]);
    float acc = 0.f;
    for (int n = n0; n < n1; n++) {
        int g = __ldg(&gid[n]);
        if (g != curg) {
            atomicAdd(&out[curg * F + j], acc);
            acc = 0.f;
            curg = g;
        }
        acc += g_x[n * F + j];
    }
    atomicAdd(&out[curg * F + j], acc);
}

// ---------------- batchnorm stats over graphs ----------------
__global__ void k_stats(const float* __restrict__ E) {
    int j = threadIdx.x;
    float s = 0.f, s2 = 0.f;
    for (int g = 0; g < NG; g++) {
        float v = E[g * F + j];
        s += v; s2 = fmaf(v, v, s2);
    }
    float mu = s * (1.f / NG);
    float var = s2 * (1.f / NG) - mu * mu;
    g_mu[j] = mu;
    g_istd[j] = rsqrtf(var + BN_EPS);
}

// ---------------- BN + MLP + log_softmax ----------------
__global__ void k_mlp(const float* __restrict__ E,
                      const float* __restrict__ gamma, const float* __restrict__ beta,
                      const float* __restrict__ fc1w, const float* __restrict__ fc1b,
                      const float* __restrict__ fc2w, const float* __restrict__ fc2b,
                      float* __restrict__ out_logits) {
    int g = blockIdx.x, j = threadIdx.x;
    __shared__ float bn[F];
    __shared__ float h[F];
    __shared__ float l[NOUT];
    __shared__ float lse;

    bn[j] = fmaf(gamma[j] * (E[g * F + j] - g_mu[j]), g_istd[j], beta[j]);
    __syncthreads();

    float acc = fc1b[j];
#pragma unroll 8
    for (int k = 0; k < F; k++) acc = fmaf(bn[k], fc1w[k * F + j], acc);
    h[j] = fmaxf(acc, 0.f);
    __syncthreads();

    if (j < NOUT) {
        float a = fc2b[j];
#pragma unroll 8
        for (int k = 0; k < F; k++) a = fmaf(h[k], fc2w[k * NOUT + j], a);
        l[j] = a;
    }
    __syncthreads();

    if (j == 0) {
        float m = -INFINITY;
        for (int o = 0; o < NOUT; o++) m = fmaxf(m, l[o]);
        float s = 0.f;
        for (int o = 0; o < NOUT; o++) s += expf(l[o] - m);
        lse = m + logf(s);
    }
    __syncthreads();

    if (j < NOUT) out_logits[g * NOUT + j] = l[j] - lse;
}

// ---------------- launch ----------------
extern "C" void kernel_launch(void* const* d_in, const int* in_sizes, int n_in,
                              void* d_out, int out_size) {
    const float* n_feat = (const float*)d_in[0];
    const int*   src    = (const int*)  d_in[1];
    const int*   dst    = (const int*)  d_in[2];
    const int*   gid    = (const int*)  d_in[3];
    const float* W1     = (const float*)d_in[4];
    const float* b1     = (const float*)d_in[5];
    const float* W2     = (const float*)d_in[6];
    const float* b2     = (const float*)d_in[7];
    const float* gamma  = (const float*)d_in[8];
    const float* beta   = (const float*)d_in[9];
    const float* fc1w   = (const float*)d_in[10];
    const float* fc1b   = (const float*)d_in[11];
    const float* fc2w   = (const float*)d_in[12];
    const float* fc2b   = (const float*)d_in[13];
    float* out = (float*)d_out;

    const int TB = 256;
    const int nodeBlocks   = (N_NODES + TB - 1) / TB;
    const int edgeBlocks   = (N_EDGES + TB - 1) / TB;
    const int gemmBlocks   = (N_NODES + 63) / 64;
    const int gatherBlocks = (N_NODES * 32 + TB - 1) / TB;     // warp per node
    const int poolBlocks   = (N_NODES + POOL_CHUNK - 1) / POOL_CHUNK;

    // degrees + norms + CSR build
    k_zero_deg<<<nodeBlocks, TB>>>();
    k_deg<<<edgeBlocks, TB>>>(src, dst);
    k_inv<<<nodeBlocks, TB>>>();
    k_scan<<<1, 1024>>>();
    k_fill<<<edgeBlocks, TB>>>(src, dst);

    // layer 1
    k_gemm<<<gemmBlocks, TB>>>(n_feat, W1, 0);
    k_gather<<<gatherBlocks, TB>>>(b1);

    // layer 2
    k_gemm<<<gemmBlocks, TB>>>(nullptr, W2, 1);
    k_gather<<<gatherBlocks, TB>>>(b2);

    // pooling into d_out embedding region (d_out is poisoned -> zero first)
    cudaMemsetAsync(out, 0, NG * F * sizeof(float), 0);
    k_pool<<<poolBlocks, F>>>(gid, out);

    // head
    k_stats<<<1, F>>>(out);
    k_mlp<<<NG, F>>>(out, gamma, beta, fc1w, fc1b, fc2w, fc2b, out + NG * F);
}

// round 6
// speedup vs baseline: 2.0522x; 1.2173x over previous
#include <cuda_runtime.h>
#include <math.h>
#include <stdint.h>

#define N_NODES 50000
#define N_EDGES 800000
#define F       128
#define NG      128
#define NOUT    10
#define BN_EPS  1e-5f

#define SCAN_B  1024
#define SCAN_NB ((N_NODES + SCAN_B - 1) / SCAN_B)   // 49

// ---------------- scratch (device globals; no runtime allocs) ----------------
__device__ float g_deg_out[N_NODES];
__device__ float g_deg_in [N_NODES];
__device__ float g_iso[N_NODES];   // rsqrt(max(deg_out,1))
__device__ float g_isi[N_NODES];   // rsqrt(max(deg_in,1))
__device__ float g_h  [N_NODES * F];   // projected features (pre-gather)
__device__ float g_x  [N_NODES * F];   // layer output
__device__ int   g_row_ptr[N_NODES + 1];
__device__ int   g_cursor [N_NODES];
__device__ int   g_csr_src[N_EDGES];
__device__ int   g_part[64];
__device__ float g_mu  [F];
__device__ float g_istd[F];

// ---------------- degrees ----------------
__global__ void k_zero_deg() {
    int i = blockIdx.x * blockDim.x + threadIdx.x;
    if (i < N_NODES) { g_deg_out[i] = 0.f; g_deg_in[i] = 0.f; }
}

__global__ void k_deg(const int* __restrict__ src, const int* __restrict__ dst) {
    int e = blockIdx.x * blockDim.x + threadIdx.x;
    if (e < N_EDGES) {
        atomicAdd(&g_deg_out[src[e]], 1.f);
        atomicAdd(&g_deg_in [dst[e]], 1.f);
    }
}

__global__ void k_inv() {
    int i = blockIdx.x * blockDim.x + threadIdx.x;
    if (i < N_NODES) {
        g_iso[i] = rsqrtf(fmaxf(g_deg_out[i], 1.f));
        g_isi[i] = rsqrtf(fmaxf(g_deg_in [i], 1.f));
    }
}

// ---------------- multi-block exclusive scan of in-degrees ----------------
// Pass 1: per-chunk scan. g_row_ptr[i] = exclusive-within-chunk; g_part[b] = chunk sum.
__global__ void k_scan1() {
    __shared__ int wsum[32];
    int tid = threadIdx.x;
    int idx = blockIdx.x * SCAN_B + tid;
    int v = (idx < N_NODES) ? (int)g_deg_in[idx] : 0;

    int x = v;
#pragma unroll
    for (int o = 1; o < 32; o <<= 1) {
        int y = __shfl_up_sync(0xFFFFFFFFu, x, o);
        if ((tid & 31) >= o) x += y;
    }
    if ((tid & 31) == 31) wsum[tid >> 5] = x;
    __syncthreads();
    if (tid < 32) {
        int w = wsum[tid];
#pragma unroll
        for (int o = 1; o < 32; o <<= 1) {
            int y = __shfl_up_sync(0xFFFFFFFFu, w, o);
            if (tid >= o) w += y;
        }
        wsum[tid] = w;
    }
    __syncthreads();

    int incl = x + ((tid >= 32) ? wsum[(tid >> 5) - 1] : 0);
    if (idx < N_NODES) g_row_ptr[idx] = incl - v;
    if (tid == SCAN_B - 1) g_part[blockIdx.x] = incl;
}

// Pass 2: exclusive scan of the 49 chunk sums (1 block, 64 threads).
__global__ void k_scan2() {
    __shared__ int sh[64];
    int t = threadIdx.x;
    int v = (t < SCAN_NB) ? g_part[t] : 0;
    sh[t] = v;
    __syncthreads();
#pragma unroll
    for (int o = 1; o < 64; o <<= 1) {
        int x = (t >= o) ? sh[t - o] : 0;
        __syncthreads();
        sh[t] += x;
        __syncthreads();
    }
    g_part[t] = sh[t] - v;                 // exclusive chunk offset
    if (t == 63) g_row_ptr[N_NODES] = sh[63];   // grand total
}

// Pass 3: add chunk offsets; init cursors.
__global__ void k_scan3() {
    int idx = blockIdx.x * SCAN_B + threadIdx.x;
    if (idx < N_NODES) {
        int e = g_row_ptr[idx] + g_part[blockIdx.x];
        g_row_ptr[idx] = e;
        g_cursor [idx] = e;
    }
}

// ---------------- bucket edges by dst ----------------
__global__ void k_fill(const int* __restrict__ src, const int* __restrict__ dst) {
    int e = blockIdx.x * blockDim.x + threadIdx.x;
    if (e < N_EDGES) {
        int d = dst[e];
        int p = atomicAdd(&g_cursor[d], 1);
        g_csr_src[p] = src[e];
    }
}

// ---------------- tf32 tensor-core GEMM ----------------
// g_h[n][j] = sum_k (X[n][k]*iso[n]) * W[k][j]
// Block: 128 threads (4 warps). Tile: M=64 (warp m16), N=64 (blockIdx.y half).
// W half pre-converted to tf32 in smem, stride 72 words (bank-conflict-free).
// A frags loaded straight from global, scaled by iso in registers.

__device__ __forceinline__ uint32_t f2tf32(float f) {
    uint32_t u;
    asm("cvt.rna.tf32.f32 %0, %1;" : "=r"(u) : "f"(f));
    return u;
}

__device__ __forceinline__ void mma_tf32(float& c0, float& c1, float& c2, float& c3,
                                         uint32_t a0, uint32_t a1, uint32_t a2, uint32_t a3,
                                         uint32_t b0, uint32_t b1) {
    asm volatile(
        "mma.sync.aligned.m16n8k8.row.col.f32.tf32.tf32.f32 "
        "{%0,%1,%2,%3}, {%4,%5,%6,%7}, {%8,%9}, {%0,%1,%2,%3};"
        : "+f"(c0), "+f"(c1), "+f"(c2), "+f"(c3)
        : "r"(a0), "r"(a1), "r"(a2), "r"(a3), "r"(b0), "r"(b1));
}

#define WS_STRIDE 72

__global__ void k_gemm(const float* __restrict__ X0, const float* __restrict__ W,
                       int use_gx) {
    const float* X = use_gx ? (const float*)g_x : X0;
    __shared__ uint32_t Ws[F][WS_STRIDE];   // tf32-converted half of W: 36.9KB

    int tid  = threadIdx.x;          // 128
    int warp = tid >> 5;
    int lane = tid & 31;
    int row0  = blockIdx.x * 64;
    int ncol0 = blockIdx.y * 64;

    // stage + convert W[:, ncol0:ncol0+64]
    for (int i = tid; i < F * 16; i += 128) {
        int k  = i >> 4;
        int f4 = i & 15;
        float4 w = *(const float4*)&W[k * F + ncol0 + f4 * 4];
        Ws[k][f4 * 4 + 0] = f2tf32(w.x);
        Ws[k][f4 * 4 + 1] = f2tf32(w.y);
        Ws[k][f4 * 4 + 2] = f2tf32(w.z);
        Ws[k][f4 * 4 + 3] = f2tf32(w.w);
    }
    __syncthreads();

    int tig = lane & 3;          // thread in group (col within k-quad)
    int grp = lane >> 2;         // group id
    int r0 = row0 + warp * 16 + grp;
    int r1 = r0 + 8;
    bool v0 = (r0 < N_NODES), v1 = (r1 < N_NODES);
    float iso0 = v0 ? g_iso[r0] : 0.f;
    float iso1 = v1 ? g_iso[r1] : 0.f;
    const float* xr0 = X + (size_t)(v0 ? r0 : 0) * F;
    const float* xr1 = X + (size_t)(v1 ? r1 : 0) * F;

    float c[8][4];
#pragma unroll
    for (int nt = 0; nt < 8; nt++)
#pragma unroll
        for (int j = 0; j < 4; j++) c[nt][j] = 0.f;

#pragma unroll
    for (int k0 = 0; k0 < F; k0 += 8) {
        int ca = k0 + tig;
        uint32_t a0 = f2tf32(v0 ? xr0[ca    ] * iso0 : 0.f);
        uint32_t a1 = f2tf32(v1 ? xr1[ca    ] * iso1 : 0.f);
        uint32_t a2 = f2tf32(v0 ? xr0[ca + 4] * iso0 : 0.f);
        uint32_t a3 = f2tf32(v1 ? xr1[ca + 4] * iso1 : 0.f);
#pragma unroll
        for (int nt = 0; nt < 8; nt++) {
            uint32_t b0 = Ws[k0 + tig    ][nt * 8 + grp];
            uint32_t b1 = Ws[k0 + 4 + tig][nt * 8 + grp];
            mma_tf32(c[nt][0], c[nt][1], c[nt][2], c[nt][3], a0, a1, a2, a3, b0, b1);
        }
    }

#pragma unroll
    for (int nt = 0; nt < 8; nt++) {
        int col = ncol0 + nt * 8 + 2 * tig;
        if (v0) *(float2*)&g_h[(size_t)r0 * F + col] = make_float2(c[nt][0], c[nt][1]);
        if (v1) *(float2*)&g_h[(size_t)r1 * F + col] = make_float2(c[nt][2], c[nt][3]);
    }
}

// ---------------- CSR gather + fused epilogue: g_x = relu(sum(h[src]) * isi + b) ----------------
__global__ void k_gather(const float* __restrict__ b) {
    int t = blockIdx.x * blockDim.x + threadIdx.x;
    int n = t >> 5, lane = t & 31;
    if (n >= N_NODES) return;

    int beg = g_row_ptr[n], end = g_row_ptr[n + 1];
    float4 acc = make_float4(0.f, 0.f, 0.f, 0.f);

    int i = beg;
    for (; i + 4 <= end; i += 4) {
        int s0 = g_csr_src[i + 0];
        int s1 = g_csr_src[i + 1];
        int s2 = g_csr_src[i + 2];
        int s3 = g_csr_src[i + 3];
        float4 v0 = *(const float4*)&g_h[s0 * F + lane * 4];
        float4 v1 = *(const float4*)&g_h[s1 * F + lane * 4];
        float4 v2 = *(const float4*)&g_h[s2 * F + lane * 4];
        float4 v3 = *(const float4*)&g_h[s3 * F + lane * 4];
        acc.x += (v0.x + v1.x) + (v2.x + v3.x);
        acc.y += (v0.y + v1.y) + (v2.y + v3.y);
        acc.z += (v0.z + v1.z) + (v2.z + v3.z);
        acc.w += (v0.w + v1.w) + (v2.w + v3.w);
    }
    for (; i < end; i++) {
        int s = g_csr_src[i];
        float4 v = *(const float4*)&g_h[s * F + lane * 4];
        acc.x += v.x; acc.y += v.y; acc.z += v.z; acc.w += v.w;
    }

    float si = g_isi[n];
    float4 bb = *(const float4*)&b[lane * 4];
    acc.x = fmaxf(fmaf(acc.x, si, bb.x), 0.f);
    acc.y = fmaxf(fmaf(acc.y, si, bb.y), 0.f);
    acc.z = fmaxf(fmaf(acc.z, si, bb.z), 0.f);
    acc.w = fmaxf(fmaf(acc.w, si, bb.w), 0.f);
    *(float4*)&g_x[n * F + lane * 4] = acc;
}

// ---------------- sum-pool exploiting sorted graph_ids ----------------
#define POOL_CHUNK 512
__global__ void k_pool(const int* __restrict__ gid, float* __restrict__ out) {
    int j = threadIdx.x;
    int n0 = blockIdx.x * POOL_CHUNK;
    int n1 = n0 + POOL_CHUNK;
    if (n1 > N_NODES) n1 = N_NODES;

    int curg = __ldg(&gid[n0]);
    float acc = 0.f;
    for (int n = n0; n < n1; n++) {
        int g = __ldg(&gid[n]);
        if (g != curg) {
            atomicAdd(&out[curg * F + j], acc);
            acc = 0.f;
            curg = g;
        }
        acc += g_x[n * F + j];
    }
    atomicAdd(&out[curg * F + j], acc);
}

// ---------------- batchnorm stats over graphs ----------------
__global__ void k_stats(const float* __restrict__ E) {
    int j = threadIdx.x;
    float s = 0.f, s2 = 0.f;
    for (int g = 0; g < NG; g++) {
        float v = E[g * F + j];
        s += v; s2 = fmaf(v, v, s2);
    }
    float mu = s * (1.f / NG);
    float var = s2 * (1.f / NG) - mu * mu;
    g_mu[j] = mu;
    g_istd[j] = rsqrtf(var + BN_EPS);
}

// ---------------- BN + MLP + log_softmax ----------------
__global__ void k_mlp(const float* __restrict__ E,
                      const float* __restrict__ gamma, const float* __restrict__ beta,
                      const float* __restrict__ fc1w, const float* __restrict__ fc1b,
                      const float* __restrict__ fc2w, const float* __restrict__ fc2b,
                      float* __restrict__ out_logits) {
    int g = blockIdx.x, j = threadIdx.x;
    __shared__ float bn[F];
    __shared__ float h[F];
    __shared__ float l[NOUT];
    __shared__ float lse;

    bn[j] = fmaf(gamma[j] * (E[g * F + j] - g_mu[j]), g_istd[j], beta[j]);
    __syncthreads();

    float acc = fc1b[j];
#pragma unroll 8
    for (int k = 0; k < F; k++) acc = fmaf(bn[k], fc1w[k * F + j], acc);
    h[j] = fmaxf(acc, 0.f);
    __syncthreads();

    if (j < NOUT) {
        float a = fc2b[j];
#pragma unroll 8
        for (int k = 0; k < F; k++) a = fmaf(h[k], fc2w[k * NOUT + j], a);
        l[j] = a;
    }
    __syncthreads();

    if (j == 0) {
        float m = -INFINITY;
        for (int o = 0; o < NOUT; o++) m = fmaxf(m, l[o]);
        float s = 0.f;
        for (int o = 0; o < NOUT; o++) s += expf(l[o] - m);
        lse = m + logf(s);
    }
    __syncthreads();

    if (j < NOUT) out_logits[g * NOUT + j] = l[j] - lse;
}

// ---------------- launch ----------------
extern "C" void kernel_launch(void* const* d_in, const int* in_sizes, int n_in,
                              void* d_out, int out_size) {
    const float* n_feat = (const float*)d_in[0];
    const int*   src    = (const int*)  d_in[1];
    const int*   dst    = (const int*)  d_in[2];
    const int*   gid    = (const int*)  d_in[3];
    const float* W1     = (const float*)d_in[4];
    const float* b1     = (const float*)d_in[5];
    const float* W2     = (const float*)d_in[6];
    const float* b2     = (const float*)d_in[7];
    const float* gamma  = (const float*)d_in[8];
    const float* beta   = (const float*)d_in[9];
    const float* fc1w   = (const float*)d_in[10];
    const float* fc1b   = (const float*)d_in[11];
    const float* fc2w   = (const float*)d_in[12];
    const float* fc2b   = (const float*)d_in[13];
    float* out = (float*)d_out;

    const int TB = 256;
    const int nodeBlocks   = (N_NODES + TB - 1) / TB;
    const int edgeBlocks   = (N_EDGES + TB - 1) / TB;
    const int gatherBlocks = (N_NODES * 32 + TB - 1) / TB;     // warp per node
    const int poolBlocks   = (N_NODES + POOL_CHUNK - 1) / POOL_CHUNK;
    dim3 gemmGrid((N_NODES + 63) / 64, 2);

    // degrees + norms + CSR build
    k_zero_deg<<<nodeBlocks, TB>>>();
    k_deg<<<edgeBlocks, TB>>>(src, dst);
    k_inv<<<nodeBlocks, TB>>>();
    k_scan1<<<SCAN_NB, SCAN_B>>>();
    k_scan2<<<1, 64>>>();
    k_scan3<<<SCAN_NB, SCAN_B>>>();
    k_fill<<<edgeBlocks, TB>>>(src, dst);

    // layer 1
    k_gemm<<<gemmGrid, 128>>>(n_feat, W1, 0);
    k_gather<<<gatherBlocks, TB>>>(b1);

    // layer 2
    k_gemm<<<gemmGrid, 128>>>(nullptr, W2, 1);
    k_gather<<<gatherBlocks, TB>>>(b2);

    // pooling into d_out embedding region (d_out is poisoned -> zero first)
    cudaMemsetAsync(out, 0, NG * F * sizeof(float), 0);
    k_pool<<<poolBlocks, F>>>(gid, out);

    // head
    k_stats<<<1, F>>>(out);
    k_mlp<<<NG, F>>>(out, gamma, beta, fc1w, fc1b, fc2w, fc2b, out + NG * F);
}

// round 7
// speedup vs baseline: 2.7625x; 1.3461x over previous
#include <cuda_runtime.h>
#include <cuda_fp16.h>
#include <math.h>
#include <stdint.h>

#define N_NODES 50000
#define N_EDGES 800000
#define F       128
#define NG      128
#define NOUT    10
#define BN_EPS  1e-5f

#define SCAN_B  1024
#define SCAN_NB ((N_NODES + SCAN_B - 1) / SCAN_B)   // 49

// ---------------- scratch (device globals; no runtime allocs) ----------------
__device__ float  g_deg_out[N_NODES];
__device__ float  g_deg_in [N_NODES];
__device__ float  g_iso[N_NODES];
__device__ float  g_isi[N_NODES];
__device__ __half g_hh [N_NODES * F];   // projected features, fp16 (pre-gather)
__device__ float  g_x  [N_NODES * F];   // layer output (fp32)
__device__ int    g_row_ptr[N_NODES + 1];
__device__ int    g_cursor [N_NODES];
__device__ int    g_csr_src[N_EDGES];
__device__ int    g_part[64];
__device__ float  g_mu  [F];
__device__ float  g_istd[F];

// ---------------- degrees ----------------
__global__ void k_zero_deg() {
    int i = blockIdx.x * blockDim.x + threadIdx.x;
    if (i < N_NODES) { g_deg_out[i] = 0.f; g_deg_in[i] = 0.f; }
}

__global__ void k_deg(const int* __restrict__ src, const int* __restrict__ dst) {
    int e = blockIdx.x * blockDim.x + threadIdx.x;
    if (e < N_EDGES) {
        atomicAdd(&g_deg_out[src[e]], 1.f);
        atomicAdd(&g_deg_in [dst[e]], 1.f);
    }
}

__global__ void k_inv() {
    int i = blockIdx.x * blockDim.x + threadIdx.x;
    if (i < N_NODES) {
        g_iso[i] = rsqrtf(fmaxf(g_deg_out[i], 1.f));
        g_isi[i] = rsqrtf(fmaxf(g_deg_in [i], 1.f));
    }
}

// ---------------- multi-block exclusive scan of in-degrees ----------------
__global__ void k_scan1() {
    __shared__ int wsum[32];
    int tid = threadIdx.x;
    int idx = blockIdx.x * SCAN_B + tid;
    int v = (idx < N_NODES) ? (int)g_deg_in[idx] : 0;

    int x = v;
#pragma unroll
    for (int o = 1; o < 32; o <<= 1) {
        int y = __shfl_up_sync(0xFFFFFFFFu, x, o);
        if ((tid & 31) >= o) x += y;
    }
    if ((tid & 31) == 31) wsum[tid >> 5] = x;
    __syncthreads();
    if (tid < 32) {
        int w = wsum[tid];
#pragma unroll
        for (int o = 1; o < 32; o <<= 1) {
            int y = __shfl_up_sync(0xFFFFFFFFu, w, o);
            if (tid >= o) w += y;
        }
        wsum[tid] = w;
    }
    __syncthreads();

    int incl = x + ((tid >= 32) ? wsum[(tid >> 5) - 1] : 0);
    if (idx < N_NODES) g_row_ptr[idx] = incl - v;
    if (tid == SCAN_B - 1) g_part[blockIdx.x] = incl;
}

__global__ void k_scan2() {
    __shared__ int sh[64];
    int t = threadIdx.x;
    int v = (t < SCAN_NB) ? g_part[t] : 0;
    sh[t] = v;
    __syncthreads();
#pragma unroll
    for (int o = 1; o < 64; o <<= 1) {
        int x = (t >= o) ? sh[t - o] : 0;
        __syncthreads();
        sh[t] += x;
        __syncthreads();
    }
    g_part[t] = sh[t] - v;
    if (t == 63) g_row_ptr[N_NODES] = sh[63];
}

__global__ void k_scan3() {
    int idx = blockIdx.x * SCAN_B + threadIdx.x;
    if (idx < N_NODES) {
        int e = g_row_ptr[idx] + g_part[blockIdx.x];
        g_row_ptr[idx] = e;
        g_cursor [idx] = e;
    }
}

// ---------------- bucket edges by dst ----------------
__global__ void k_fill(const int* __restrict__ src, const int* __restrict__ dst) {
    int e = blockIdx.x * blockDim.x + threadIdx.x;
    if (e < N_EDGES) {
        int d = dst[e];
        int p = atomicAdd(&g_cursor[d], 1);
        g_csr_src[p] = src[e];
    }
}

// ---------------- tf32 tensor-core GEMM, fp16 output ----------------
__device__ __forceinline__ uint32_t f2tf32(float f) {
    uint32_t u;
    asm("cvt.rna.tf32.f32 %0, %1;" : "=r"(u) : "f"(f));
    return u;
}

__device__ __forceinline__ void mma_tf32(float& c0, float& c1, float& c2, float& c3,
                                         uint32_t a0, uint32_t a1, uint32_t a2, uint32_t a3,
                                         uint32_t b0, uint32_t b1) {
    asm volatile(
        "mma.sync.aligned.m16n8k8.row.col.f32.tf32.tf32.f32 "
        "{%0,%1,%2,%3}, {%4,%5,%6,%7}, {%8,%9}, {%0,%1,%2,%3};"
        : "+f"(c0), "+f"(c1), "+f"(c2), "+f"(c3)
        : "r"(a0), "r"(a1), "r"(a2), "r"(a3), "r"(b0), "r"(b1));
}

#define WS_STRIDE 72

__global__ void k_gemm(const float* __restrict__ X0, const float* __restrict__ W,
                       int use_gx) {
    const float* X = use_gx ? (const float*)g_x : X0;
    __shared__ uint32_t Ws[F][WS_STRIDE];

    int tid  = threadIdx.x;          // 128
    int warp = tid >> 5;
    int lane = tid & 31;
    int row0  = blockIdx.x * 64;
    int ncol0 = blockIdx.y * 64;

    for (int i = tid; i < F * 16; i += 128) {
        int k  = i >> 4;
        int f4 = i & 15;
        float4 w = *(const float4*)&W[k * F + ncol0 + f4 * 4];
        Ws[k][f4 * 4 + 0] = f2tf32(w.x);
        Ws[k][f4 * 4 + 1] = f2tf32(w.y);
        Ws[k][f4 * 4 + 2] = f2tf32(w.z);
        Ws[k][f4 * 4 + 3] = f2tf32(w.w);
    }
    __syncthreads();

    int tig = lane & 3;
    int grp = lane >> 2;
    int r0 = row0 + warp * 16 + grp;
    int r1 = r0 + 8;
    bool v0 = (r0 < N_NODES), v1 = (r1 < N_NODES);
    float iso0 = v0 ? g_iso[r0] : 0.f;
    float iso1 = v1 ? g_iso[r1] : 0.f;
    const float* xr0 = X + (size_t)(v0 ? r0 : 0) * F;
    const float* xr1 = X + (size_t)(v1 ? r1 : 0) * F;

    float c[8][4];
#pragma unroll
    for (int nt = 0; nt < 8; nt++)
#pragma unroll
        for (int j = 0; j < 4; j++) c[nt][j] = 0.f;

#pragma unroll
    for (int k0 = 0; k0 < F; k0 += 8) {
        int ca = k0 + tig;
        uint32_t a0 = f2tf32(v0 ? xr0[ca    ] * iso0 : 0.f);
        uint32_t a1 = f2tf32(v1 ? xr1[ca    ] * iso1 : 0.f);
        uint32_t a2 = f2tf32(v0 ? xr0[ca + 4] * iso0 : 0.f);
        uint32_t a3 = f2tf32(v1 ? xr1[ca + 4] * iso1 : 0.f);
#pragma unroll
        for (int nt = 0; nt < 8; nt++) {
            uint32_t b0 = Ws[k0 + tig    ][nt * 8 + grp];
            uint32_t b1 = Ws[k0 + 4 + tig][nt * 8 + grp];
            mma_tf32(c[nt][0], c[nt][1], c[nt][2], c[nt][3], a0, a1, a2, a3, b0, b1);
        }
    }

#pragma unroll
    for (int nt = 0; nt < 8; nt++) {
        int col = ncol0 + nt * 8 + 2 * tig;
        if (v0) *(__half2*)&g_hh[(size_t)r0 * F + col] = __floats2half2_rn(c[nt][0], c[nt][1]);
        if (v1) *(__half2*)&g_hh[(size_t)r1 * F + col] = __floats2half2_rn(c[nt][2], c[nt][3]);
    }
}

// ---------------- CSR gather (fp16 in, fp32 accum) + fused epilogue ----------------
// Half-warp (16 lanes) per node; lane covers 8 features (uint4 = 8 halves).
__global__ void k_gather(const float* __restrict__ b) {
    int t = blockIdx.x * blockDim.x + threadIdx.x;
    int n = t >> 4, sub = t & 15;
    if (n >= N_NODES) return;

    int beg = g_row_ptr[n], end = g_row_ptr[n + 1];
    const uint4* hh = (const uint4*)g_hh;   // row stride = 16 uint4

    float acc[8];
#pragma unroll
    for (int d = 0; d < 8; d++) acc[d] = 0.f;

    int i = beg;
    for (; i + 4 <= end; i += 4) {
        int s0 = g_csr_src[i + 0];
        int s1 = g_csr_src[i + 1];
        int s2 = g_csr_src[i + 2];
        int s3 = g_csr_src[i + 3];
        uint4 v0 = hh[s0 * 16 + sub];
        uint4 v1 = hh[s1 * 16 + sub];
        uint4 v2 = hh[s2 * 16 + sub];
        uint4 v3 = hh[s3 * 16 + sub];
#pragma unroll
        for (int q = 0; q < 4; q++) {
            uint32_t w0 = (&v0.x)[q], w1 = (&v1.x)[q], w2 = (&v2.x)[q], w3 = (&v3.x)[q];
            float2 f0 = __half22float2(*(__half2*)&w0);
            float2 f1 = __half22float2(*(__half2*)&w1);
            float2 f2 = __half22float2(*(__half2*)&w2);
            float2 f3 = __half22float2(*(__half2*)&w3);
            acc[2 * q + 0] += (f0.x + f1.x) + (f2.x + f3.x);
            acc[2 * q + 1] += (f0.y + f1.y) + (f2.y + f3.y);
        }
    }
    for (; i < end; i++) {
        int s = g_csr_src[i];
        uint4 v = hh[s * 16 + sub];
#pragma unroll
        for (int q = 0; q < 4; q++) {
            uint32_t w = (&v.x)[q];
            float2 f = __half22float2(*(__half2*)&w);
            acc[2 * q + 0] += f.x;
            acc[2 * q + 1] += f.y;
        }
    }

    float si = g_isi[n];
    float4 b0 = *(const float4*)&b[sub * 8];
    float4 b1 = *(const float4*)&b[sub * 8 + 4];
    float4 o0, o1;
    o0.x = fmaxf(fmaf(acc[0], si, b0.x), 0.f);
    o0.y = fmaxf(fmaf(acc[1], si, b0.y), 0.f);
    o0.z = fmaxf(fmaf(acc[2], si, b0.z), 0.f);
    o0.w = fmaxf(fmaf(acc[3], si, b0.w), 0.f);
    o1.x = fmaxf(fmaf(acc[4], si, b1.x), 0.f);
    o1.y = fmaxf(fmaf(acc[5], si, b1.y), 0.f);
    o1.z = fmaxf(fmaf(acc[6], si, b1.z), 0.f);
    o1.w = fmaxf(fmaf(acc[7], si, b1.w), 0.f);
    *(float4*)&g_x[(size_t)n * F + sub * 8    ] = o0;
    *(float4*)&g_x[(size_t)n * F + sub * 8 + 4] = o1;
}

// ---------------- sum-pool exploiting sorted graph_ids ----------------
#define POOL_CHUNK 256
__global__ void k_pool(const int* __restrict__ gid, float* __restrict__ out) {
    int j = threadIdx.x;
    int n0 = blockIdx.x * POOL_CHUNK;
    int n1 = n0 + POOL_CHUNK;
    if (n1 > N_NODES) n1 = N_NODES;

    int curg = __ldg(&gid[n0]);
    float acc = 0.f;
    for (int n = n0; n < n1; n++) {
        int g = __ldg(&gid[n]);
        if (g != curg) {
            atomicAdd(&out[curg * F + j], acc);
            acc = 0.f;
            curg = g;
        }
        acc += g_x[(size_t)n * F + j];
    }
    atomicAdd(&out[curg * F + j], acc);
}

// ---------------- batchnorm stats ----------------
__global__ void k_stats(const float* __restrict__ E) {
    int j = threadIdx.x;
    float s = 0.f, s2 = 0.f;
    for (int g = 0; g < NG; g++) {
        float v = E[g * F + j];
        s += v; s2 = fmaf(v, v, s2);
    }
    float mu = s * (1.f / NG);
    float var = s2 * (1.f / NG) - mu * mu;
    g_mu[j] = mu;
    g_istd[j] = rsqrtf(var + BN_EPS);
}

// ---------------- BN + MLP + log_softmax ----------------
__global__ void k_mlp(const float* __restrict__ E,
                      const float* __restrict__ gamma, const float* __restrict__ beta,
                      const float* __restrict__ fc1w, const float* __restrict__ fc1b,
                      const float* __restrict__ fc2w, const float* __restrict__ fc2b,
                      float* __restrict__ out_logits) {
    int g = blockIdx.x, j = threadIdx.x;
    __shared__ float bn[F];
    __shared__ float h[F];
    __shared__ float l[NOUT];
    __shared__ float lse;

    bn[j] = fmaf(gamma[j] * (E[g * F + j] - g_mu[j]), g_istd[j], beta[j]);
    __syncthreads();

    float acc = fc1b[j];
#pragma unroll 8
    for (int k = 0; k < F; k++) acc = fmaf(bn[k], fc1w[k * F + j], acc);
    h[j] = fmaxf(acc, 0.f);
    __syncthreads();

    if (j < NOUT) {
        float a = fc2b[j];
#pragma unroll 8
        for (int k = 0; k < F; k++) a = fmaf(h[k], fc2w[k * NOUT + j], a);
        l[j] = a;
    }
    __syncthreads();

    if (j == 0) {
        float m = -INFINITY;
        for (int o = 0; o < NOUT; o++) m = fmaxf(m, l[o]);
        float s = 0.f;
        for (int o = 0; o < NOUT; o++) s += expf(l[o] - m);
        lse = m + logf(s);
    }
    __syncthreads();

    if (j < NOUT) out_logits[g * NOUT + j] = l[j] - lse;
}

// ---------------- launch ----------------
extern "C" void kernel_launch(void* const* d_in, const int* in_sizes, int n_in,
                              void* d_out, int out_size) {
    const float* n_feat = (const float*)d_in[0];
    const int*   src    = (const int*)  d_in[1];
    const int*   dst    = (const int*)  d_in[2];
    const int*   gid    = (const int*)  d_in[3];
    const float* W1     = (const float*)d_in[4];
    const float* b1     = (const float*)d_in[5];
    const float* W2     = (const float*)d_in[6];
    const float* b2     = (const float*)d_in[7];
    const float* gamma  = (const float*)d_in[8];
    const float* beta   = (const float*)d_in[9];
    const float* fc1w   = (const float*)d_in[10];
    const float* fc1b   = (const float*)d_in[11];
    const float* fc2w   = (const float*)d_in[12];
    const float* fc2b   = (const float*)d_in[13];
    float* out = (float*)d_out;

    const int TB = 256;
    const int nodeBlocks   = (N_NODES + TB - 1) / TB;
    const int edgeBlocks   = (N_EDGES + TB - 1) / TB;
    const int gatherBlocks = (N_NODES * 16 + TB - 1) / TB;   // half-warp per node
    const int poolBlocks   = (N_NODES + POOL_CHUNK - 1) / POOL_CHUNK;
    dim3 gemmGrid((N_NODES + 63) / 64, 2);

    // degrees + norms + CSR build
    k_zero_deg<<<nodeBlocks, TB>>>();
    k_deg<<<edgeBlocks, TB>>>(src, dst);
    k_inv<<<nodeBlocks, TB>>>();
    k_scan1<<<SCAN_NB, SCAN_B>>>();
    k_scan2<<<1, 64>>>();
    k_scan3<<<SCAN_NB, SCAN_B>>>();
    k_fill<<<edgeBlocks, TB>>>(src, dst);

    // layer 1
    k_gemm<<<gemmGrid, 128>>>(n_feat, W1, 0);
    k_gather<<<gatherBlocks, TB>>>(b1);

    // layer 2
    k_gemm<<<gemmGrid, 128>>>(nullptr, W2, 1);
    k_gather<<<gatherBlocks, TB>>>(b2);

    // pooling into d_out embedding region (d_out is poisoned -> zero first)
    cudaMemsetAsync(out, 0, NG * F * sizeof(float), 0);
    k_pool<<<poolBlocks, F>>>(gid, out);

    // head
    k_stats<<<1, F>>>(out);
    k_mlp<<<NG, F>>>(out, gamma, beta, fc1w, fc1b, fc2w, fc2b, out + NG * F);
}

// round 8
// speedup vs baseline: 3.1038x; 1.1235x over previous
#include <cuda_runtime.h>
#include <cuda_fp16.h>
#include <math.h>
#include <stdint.h>

#define N_NODES 50000
#define N_EDGES 800000
#define F       128
#define NG      128
#define NOUT    10
#define BN_EPS  1e-5f

#define SCAN_B  1024
#define SCAN_NB ((N_NODES + SCAN_B - 1) / SCAN_B)   // 49

// ---------------- scratch (device globals; no runtime allocs) ----------------
__device__ float  g_deg_out[N_NODES];
__device__ float  g_deg_in [N_NODES];
__device__ float  g_iso[N_NODES];
__device__ float  g_isi[N_NODES];
__device__ __half g_hh [N_NODES * F];   // X@W (UNscaled), fp16
__device__ float  g_x  [N_NODES * F];   // layer output (fp32)
__device__ int    g_row_ptr[N_NODES + 1];
__device__ int    g_cursor [N_NODES];
__device__ int    g_csr_src[N_EDGES];
__device__ int    g_part[64];
__device__ float  g_mu  [F];
__device__ float  g_istd[F];

// ---------------- degrees ----------------
__global__ void k_zero_deg() {
    int i = blockIdx.x * blockDim.x + threadIdx.x;
    if (i < N_NODES) { g_deg_out[i] = 0.f; g_deg_in[i] = 0.f; }
}

__global__ void k_deg(const int* __restrict__ src, const int* __restrict__ dst) {
    int e = blockIdx.x * blockDim.x + threadIdx.x;
    if (e < N_EDGES) {
        atomicAdd(&g_deg_out[src[e]], 1.f);
        atomicAdd(&g_deg_in [dst[e]], 1.f);
    }
}

// ---------------- scan pass 1 (+ fused inv-sqrt norms) ----------------
__global__ void k_scan1() {
    __shared__ int wsum[32];
    int tid = threadIdx.x;
    int idx = blockIdx.x * SCAN_B + tid;
    int v = 0;
    if (idx < N_NODES) {
        float din = g_deg_in[idx];
        v = (int)din;
        g_iso[idx] = rsqrtf(fmaxf(g_deg_out[idx], 1.f));
        g_isi[idx] = rsqrtf(fmaxf(din, 1.f));
    }

    int x = v;
#pragma unroll
    for (int o = 1; o < 32; o <<= 1) {
        int y = __shfl_up_sync(0xFFFFFFFFu, x, o);
        if ((tid & 31) >= o) x += y;
    }
    if ((tid & 31) == 31) wsum[tid >> 5] = x;
    __syncthreads();
    if (tid < 32) {
        int w = wsum[tid];
#pragma unroll
        for (int o = 1; o < 32; o <<= 1) {
            int y = __shfl_up_sync(0xFFFFFFFFu, w, o);
            if (tid >= o) w += y;
        }
        wsum[tid] = w;
    }
    __syncthreads();

    int incl = x + ((tid >= 32) ? wsum[(tid >> 5) - 1] : 0);
    if (idx < N_NODES) g_row_ptr[idx] = incl - v;
    if (tid == SCAN_B - 1) g_part[blockIdx.x] = incl;
}

__global__ void k_scan2() {
    __shared__ int sh[64];
    int t = threadIdx.x;
    int v = (t < SCAN_NB) ? g_part[t] : 0;
    sh[t] = v;
    __syncthreads();
#pragma unroll
    for (int o = 1; o < 64; o <<= 1) {
        int x = (t >= o) ? sh[t - o] : 0;
        __syncthreads();
        sh[t] += x;
        __syncthreads();
    }
    g_part[t] = sh[t] - v;
    if (t == 63) g_row_ptr[N_NODES] = sh[63];
}

__global__ void k_scan3() {
    int idx = blockIdx.x * SCAN_B + threadIdx.x;
    if (idx < N_NODES) {
        int e = g_row_ptr[idx] + g_part[blockIdx.x];
        g_row_ptr[idx] = e;
        g_cursor [idx] = e;
    }
}

__global__ void k_fill(const int* __restrict__ src, const int* __restrict__ dst) {
    int e = blockIdx.x * blockDim.x + threadIdx.x;
    if (e < N_EDGES) {
        int d = dst[e];
        int p = atomicAdd(&g_cursor[d], 1);
        g_csr_src[p] = src[e];
    }
}

// ---------------- tf32 tensor-core GEMM (no iso scaling), fp16 out ----------------
// 128 rows x 128 cols per block, 256 threads (8 warps), full W in dyn smem.
__device__ __forceinline__ uint32_t f2tf32(float f) {
    uint32_t u;
    asm("cvt.rna.tf32.f32 %0, %1;" : "=r"(u) : "f"(f));
    return u;
}

__device__ __forceinline__ void mma_tf32(float& c0, float& c1, float& c2, float& c3,
                                         uint32_t a0, uint32_t a1, uint32_t a2, uint32_t a3,
                                         uint32_t b0, uint32_t b1) {
    asm volatile(
        "mma.sync.aligned.m16n8k8.row.col.f32.tf32.tf32.f32 "
        "{%0,%1,%2,%3}, {%4,%5,%6,%7}, {%8,%9}, {%0,%1,%2,%3};"
        : "+f"(c0), "+f"(c1), "+f"(c2), "+f"(c3)
        : "r"(a0), "r"(a1), "r"(a2), "r"(a3), "r"(b0), "r"(b1));
}

#define BS_STRIDE 132
#define SMEM_GEMM (F * BS_STRIDE * 4)    // 67584 bytes

__global__ __launch_bounds__(256, 1) void k_gemm(const float* __restrict__ X0,
                                                 const float* __restrict__ W,
                                                 int use_gx) {
    const float* X = use_gx ? (const float*)g_x : X0;
    extern __shared__ uint32_t Bs[];    // [F][BS_STRIDE], layout col -> grp*16 + nt

    int tid  = threadIdx.x;
    int warp = tid >> 5;
    int lane = tid & 31;
    int row0 = blockIdx.x * 128;

    // stage + convert full W (128x128) with b-frag friendly layout
    for (int i = tid; i < F * 32; i += 256) {
        int k  = i >> 5;
        int f4 = i & 31;
        float4 w = *(const float4*)&W[k * F + f4 * 4];
        int c0 = f4 * 4;
#pragma unroll
        for (int j = 0; j < 4; j++) {
            int c = c0 + j;
            float val = (&w.x)[j];
            Bs[k * BS_STRIDE + (c & 7) * 16 + (c >> 3)] = f2tf32(val);
        }
    }
    __syncthreads();

    int tig = lane & 3;
    int grp = lane >> 2;
    int r0 = row0 + warp * 16 + grp;
    int r1 = r0 + 8;
    bool v0 = (r0 < N_NODES), v1 = (r1 < N_NODES);
    const float* xr0 = X + (size_t)(v0 ? r0 : 0) * F;
    const float* xr1 = X + (size_t)(v1 ? r1 : 0) * F;

    float c[16][4];
#pragma unroll
    for (int nt = 0; nt < 16; nt++)
#pragma unroll
        for (int j = 0; j < 4; j++) c[nt][j] = 0.f;

    // double-buffered A loads
    float af[2][4];
    {
        int ca = tig;
        af[0][0] = v0 ? xr0[ca    ] : 0.f;
        af[0][1] = v1 ? xr1[ca    ] : 0.f;
        af[0][2] = v0 ? xr0[ca + 4] : 0.f;
        af[0][3] = v1 ? xr1[ca + 4] : 0.f;
    }

#pragma unroll
    for (int kk = 0; kk < 16; kk++) {
        int k0 = kk * 8;
        if (kk + 1 < 16) {
            int ca = k0 + 8 + tig;
            af[(kk + 1) & 1][0] = v0 ? xr0[ca    ] : 0.f;
            af[(kk + 1) & 1][1] = v1 ? xr1[ca    ] : 0.f;
            af[(kk + 1) & 1][2] = v0 ? xr0[ca + 4] : 0.f;
            af[(kk + 1) & 1][3] = v1 ? xr1[ca + 4] : 0.f;
        }
        uint32_t a0 = f2tf32(af[kk & 1][0]);
        uint32_t a1 = f2tf32(af[kk & 1][1]);
        uint32_t a2 = f2tf32(af[kk & 1][2]);
        uint32_t a3 = f2tf32(af[kk & 1][3]);

        const uint32_t* b0p = &Bs[(k0 + tig    ) * BS_STRIDE + grp * 16];
        const uint32_t* b1p = &Bs[(k0 + 4 + tig) * BS_STRIDE + grp * 16];
#pragma unroll
        for (int ntg = 0; ntg < 4; ntg++) {
            uint4 p0 = *(const uint4*)(b0p + ntg * 4);
            uint4 p1 = *(const uint4*)(b1p + ntg * 4);
            int nt = ntg * 4;
            mma_tf32(c[nt+0][0], c[nt+0][1], c[nt+0][2], c[nt+0][3], a0,a1,a2,a3, p0.x, p1.x);
            mma_tf32(c[nt+1][0], c[nt+1][1], c[nt+1][2], c[nt+1][3], a0,a1,a2,a3, p0.y, p1.y);
            mma_tf32(c[nt+2][0], c[nt+2][1], c[nt+2][2], c[nt+2][3], a0,a1,a2,a3, p0.z, p1.z);
            mma_tf32(c[nt+3][0], c[nt+3][1], c[nt+3][2], c[nt+3][3], a0,a1,a2,a3, p0.w, p1.w);
        }
    }

#pragma unroll
    for (int nt = 0; nt < 16; nt++) {
        int col = nt * 8 + 2 * tig;
        if (v0) *(__half2*)&g_hh[(size_t)r0 * F + col] = __floats2half2_rn(c[nt][0], c[nt][1]);
        if (v1) *(__half2*)&g_hh[(size_t)r1 * F + col] = __floats2half2_rn(c[nt][2], c[nt][3]);
    }
}

// ---------------- CSR gather: acc += iso[src]*h[src]; out = relu(acc*isi + b) ----------------
__global__ void k_gather(const float* __restrict__ b) {
    int t = blockIdx.x * blockDim.x + threadIdx.x;
    int n = t >> 4, sub = t & 15;
    if (n >= N_NODES) return;

    int beg = g_row_ptr[n], end = g_row_ptr[n + 1];
    const uint4* hh = (const uint4*)g_hh;   // row stride = 16 uint4

    float acc[8];
#pragma unroll
    for (int d = 0; d < 8; d++) acc[d] = 0.f;

    int i = beg;
    for (; i + 4 <= end; i += 4) {
        int s0 = g_csr_src[i + 0];
        int s1 = g_csr_src[i + 1];
        int s2 = g_csr_src[i + 2];
        int s3 = g_csr_src[i + 3];
        float w0 = g_iso[s0], w1 = g_iso[s1], w2 = g_iso[s2], w3 = g_iso[s3];
        uint4 v0 = hh[s0 * 16 + sub];
        uint4 v1 = hh[s1 * 16 + sub];
        uint4 v2 = hh[s2 * 16 + sub];
        uint4 v3 = hh[s3 * 16 + sub];
#pragma unroll
        for (int q = 0; q < 4; q++) {
            uint32_t x0 = (&v0.x)[q], x1 = (&v1.x)[q], x2 = (&v2.x)[q], x3 = (&v3.x)[q];
            float2 f0 = __half22float2(*(__half2*)&x0);
            float2 f1 = __half22float2(*(__half2*)&x1);
            float2 f2 = __half22float2(*(__half2*)&x2);
            float2 f3 = __half22float2(*(__half2*)&x3);
            acc[2*q+0] = fmaf(f0.x, w0, fmaf(f1.x, w1, fmaf(f2.x, w2, fmaf(f3.x, w3, acc[2*q+0]))));
            acc[2*q+1] = fmaf(f0.y, w0, fmaf(f1.y, w1, fmaf(f2.y, w2, fmaf(f3.y, w3, acc[2*q+1]))));
        }
    }
    for (; i < end; i++) {
        int s = g_csr_src[i];
        float w = g_iso[s];
        uint4 v = hh[s * 16 + sub];
#pragma unroll
        for (int q = 0; q < 4; q++) {
            uint32_t x = (&v.x)[q];
            float2 f = __half22float2(*(__half2*)&x);
            acc[2*q+0] = fmaf(f.x, w, acc[2*q+0]);
            acc[2*q+1] = fmaf(f.y, w, acc[2*q+1]);
        }
    }

    float si = g_isi[n];
    float4 b0 = *(const float4*)&b[sub * 8];
    float4 b1 = *(const float4*)&b[sub * 8 + 4];
    float4 o0, o1;
    o0.x = fmaxf(fmaf(acc[0], si, b0.x), 0.f);
    o0.y = fmaxf(fmaf(acc[1], si, b0.y), 0.f);
    o0.z = fmaxf(fmaf(acc[2], si, b0.z), 0.f);
    o0.w = fmaxf(fmaf(acc[3], si, b0.w), 0.f);
    o1.x = fmaxf(fmaf(acc[4], si, b1.x), 0.f);
    o1.y = fmaxf(fmaf(acc[5], si, b1.y), 0.f);
    o1.z = fmaxf(fmaf(acc[6], si, b1.z), 0.f);
    o1.w = fmaxf(fmaf(acc[7], si, b1.w), 0.f);
    *(float4*)&g_x[(size_t)n * F + sub * 8    ] = o0;
    *(float4*)&g_x[(size_t)n * F + sub * 8 + 4] = o1;
}

// ---------------- sum-pool exploiting sorted graph_ids ----------------
#define POOL_CHUNK 256
__global__ void k_pool(const int* __restrict__ gid, float* __restrict__ out) {
    int j = threadIdx.x;
    int n0 = blockIdx.x * POOL_CHUNK;
    int n1 = n0 + POOL_CHUNK;
    if (n1 > N_NODES) n1 = N_NODES;

    int curg = __ldg(&gid[n0]);
    float acc = 0.f;
    for (int n = n0; n < n1; n++) {
        int g = __ldg(&gid[n]);
        if (g != curg) {
            atomicAdd(&out[curg * F + j], acc);
            acc = 0.f;
            curg = g;
        }
        acc += g_x[(size_t)n * F + j];
    }
    atomicAdd(&out[curg * F + j], acc);
}

// ---------------- batchnorm stats ----------------
__global__ void k_stats(const float* __restrict__ E) {
    int j = threadIdx.x;
    float s = 0.f, s2 = 0.f;
    for (int g = 0; g < NG; g++) {
        float v = E[g * F + j];
        s += v; s2 = fmaf(v, v, s2);
    }
    float mu = s * (1.f / NG);
    float var = s2 * (1.f / NG) - mu * mu;
    g_mu[j] = mu;
    g_istd[j] = rsqrtf(var + BN_EPS);
}

// ---------------- BN + MLP + log_softmax ----------------
__global__ void k_mlp(const float* __restrict__ E,
                      const float* __restrict__ gamma, const float* __restrict__ beta,
                      const float* __restrict__ fc1w, const float* __restrict__ fc1b,
                      const float* __restrict__ fc2w, const float* __restrict__ fc2b,
                      float* __restrict__ out_logits) {
    int g = blockIdx.x, j = threadIdx.x;
    __shared__ float bn[F];
    __shared__ float h[F];
    __shared__ float l[NOUT];
    __shared__ float lse;

    bn[j] = fmaf(gamma[j] * (E[g * F + j] - g_mu[j]), g_istd[j], beta[j]);
    __syncthreads();

    float acc = fc1b[j];
#pragma unroll 8
    for (int k = 0; k < F; k++) acc = fmaf(bn[k], fc1w[k * F + j], acc);
    h[j] = fmaxf(acc, 0.f);
    __syncthreads();

    if (j < NOUT) {
        float a = fc2b[j];
#pragma unroll 8
        for (int k = 0; k < F; k++) a = fmaf(h[k], fc2w[k * NOUT + j], a);
        l[j] = a;
    }
    __syncthreads();

    if (j == 0) {
        float m = -INFINITY;
        for (int o = 0; o < NOUT; o++) m = fmaxf(m, l[o]);
        float s = 0.f;
        for (int o = 0; o < NOUT; o++) s += expf(l[o] - m);
        lse = m + logf(s);
    }
    __syncthreads();

    if (j < NOUT) out_logits[g * NOUT + j] = l[j] - lse;
}

// ---------------- launch ----------------
extern "C" void kernel_launch(void* const* d_in, const int* in_sizes, int n_in,
                              void* d_out, int out_size) {
    const float* n_feat = (const float*)d_in[0];
    const int*   src    = (const int*)  d_in[1];
    const int*   dst    = (const int*)  d_in[2];
    const int*   gid    = (const int*)  d_in[3];
    const float* W1     = (const float*)d_in[4];
    const float* b1     = (const float*)d_in[5];
    const float* W2     = (const float*)d_in[6];
    const float* b2     = (const float*)d_in[7];
    const float* gamma  = (const float*)d_in[8];
    const float* beta   = (const float*)d_in[9];
    const float* fc1w   = (const float*)d_in[10];
    const float* fc1b   = (const float*)d_in[11];
    const float* fc2w   = (const float*)d_in[12];
    const float* fc2b   = (const float*)d_in[13];
    float* out = (float*)d_out;

    // one-time handle setup (handles only; no device memory, no cached work)
    static cudaStream_t s_side = nullptr;
    static cudaEvent_t  evRoot = nullptr, evSide = nullptr;
    if (s_side == nullptr) {
        cudaStreamCreateWithFlags(&s_side, cudaStreamNonBlocking);
        cudaEventCreateWithFlags(&evRoot, cudaEventDisableTiming);
        cudaEventCreateWithFlags(&evSide, cudaEventDisableTiming);
        cudaFuncSetAttribute(k_gemm, cudaFuncAttributeMaxDynamicSharedMemorySize, SMEM_GEMM);
    }

    const int TB = 256;
    const int nodeBlocks   = (N_NODES + TB - 1) / TB;
    const int edgeBlocks   = (N_EDGES + TB - 1) / TB;
    const int gatherBlocks = (N_NODES * 16 + TB - 1) / TB;
    const int poolBlocks   = (N_NODES + POOL_CHUNK - 1) / POOL_CHUNK;
    const int gemmBlocks   = (N_NODES + 127) / 128;

    // fork: GEMM-1 (independent of degrees now) runs beside the CSR build
    cudaEventRecord(evRoot, 0);
    cudaStreamWaitEvent(s_side, evRoot, 0);
    k_gemm<<<gemmBlocks, 256, SMEM_GEMM, s_side>>>(n_feat, W1, 0);
    cudaEventRecord(evSide, s_side);

    // CSR build on main stream
    k_zero_deg<<<nodeBlocks, TB>>>();
    k_deg<<<edgeBlocks, TB>>>(src, dst);
    k_scan1<<<SCAN_NB, SCAN_B>>>();
    k_scan2<<<1, 64>>>();
    k_scan3<<<SCAN_NB, SCAN_B>>>();
    k_fill<<<edgeBlocks, TB>>>(src, dst);

    // join, then layer 1 aggregate
    cudaStreamWaitEvent(0, evSide, 0);
    k_gather<<<gatherBlocks, TB>>>(b1);

    // layer 2
    k_gemm<<<gemmBlocks, 256, SMEM_GEMM>>>(nullptr, W2, 1);
    k_gather<<<gatherBlocks, TB>>>(b2);

    // pooling into d_out embedding region (d_out is poisoned -> zero first)
    cudaMemsetAsync(out, 0, NG * F * sizeof(float), 0);
    k_pool<<<poolBlocks, F>>>(gid, out);

    // head
    k_stats<<<1, F>>>(out);
    k_mlp<<<NG, F>>>(out, gamma, beta, fc1w, fc1b, fc2w, fc2b, out + NG * F);
}

// round 10
// speedup vs baseline: 3.3008x; 1.0635x over previous
#include <cuda_runtime.h>
#include <cuda_fp16.h>
#include <math.h>
#include <stdint.h>

#define N_NODES 50000
#define N_EDGES 800000
#define F       128
#define NG      128
#define NOUT    10
#define BN_EPS  1e-5f

#define SCAN_B  1024
#define SCAN_NB ((N_NODES + SCAN_B - 1) / SCAN_B)   // 49

// ---------------- scratch (device globals; no runtime allocs) ----------------
__device__ float  g_deg_out[N_NODES];
__device__ float  g_deg_in [N_NODES];
__device__ float  g_iso[N_NODES];
__device__ float  g_isi[N_NODES];
__device__ __half g_hh [N_NODES * F];   // X@W (unscaled), fp16 (pre-gather)
__device__ __half g_xh [N_NODES * F];   // layer-1 output, fp16 (GEMM-2 A operand)
__device__ float  g_x  [N_NODES * F];   // layer-2 output, fp32 (pool input)
__device__ int    g_row_ptr[N_NODES + 1];
__device__ int    g_cursor [N_NODES];
__device__ int    g_csr_src[N_EDGES];
__device__ int    g_part[64];

// ---------------- degrees ----------------
__global__ void k_zero_deg() {
    int i = blockIdx.x * blockDim.x + threadIdx.x;
    if (i < N_NODES) { g_deg_out[i] = 0.f; g_deg_in[i] = 0.f; }
}

__global__ void k_deg(const int* __restrict__ src, const int* __restrict__ dst) {
    int e = blockIdx.x * blockDim.x + threadIdx.x;
    if (e < N_EDGES) {
        atomicAdd(&g_deg_out[src[e]], 1.f);
        atomicAdd(&g_deg_in [dst[e]], 1.f);
    }
}

// ---------------- scan pass 1 (+ fused inv-sqrt norms) ----------------
__global__ void k_scan1() {
    __shared__ int wsum[32];
    int tid = threadIdx.x;
    int idx = blockIdx.x * SCAN_B + tid;
    int v = 0;
    if (idx < N_NODES) {
        float din = g_deg_in[idx];
        v = (int)din;
        g_iso[idx] = rsqrtf(fmaxf(g_deg_out[idx], 1.f));
        g_isi[idx] = rsqrtf(fmaxf(din, 1.f));
    }

    int x = v;
#pragma unroll
    for (int o = 1; o < 32; o <<= 1) {
        int y = __shfl_up_sync(0xFFFFFFFFu, x, o);
        if ((tid & 31) >= o) x += y;
    }
    if ((tid & 31) == 31) wsum[tid >> 5] = x;
    __syncthreads();
    if (tid < 32) {
        int w = wsum[tid];
#pragma unroll
        for (int o = 1; o < 32; o <<= 1) {
            int y = __shfl_up_sync(0xFFFFFFFFu, w, o);
            if (tid >= o) w += y;
        }
        wsum[tid] = w;
    }
    __syncthreads();

    int incl = x + ((tid >= 32) ? wsum[(tid >> 5) - 1] : 0);
    if (idx < N_NODES) g_row_ptr[idx] = incl - v;
    if (tid == SCAN_B - 1) g_part[blockIdx.x] = incl;
}

// ---------------- scan pass 2+3 fused: each block self-scans the partials ----------------
__global__ void k_scan3() {
    __shared__ int sh[64];
    int tid = threadIdx.x;
    if (tid < 64) sh[tid] = (tid < SCAN_NB) ? g_part[tid] : 0;
    __syncthreads();
#pragma unroll
    for (int o = 1; o < 64; o <<= 1) {
        int x = 0;
        if (tid < 64 && tid >= o) x = sh[tid - o];
        __syncthreads();
        if (tid < 64) sh[tid] += x;
        __syncthreads();
    }
    int off = (blockIdx.x == 0) ? 0 : sh[blockIdx.x - 1];
    int idx = blockIdx.x * SCAN_B + tid;
    if (idx < N_NODES) {
        int e = g_row_ptr[idx] + off;
        g_row_ptr[idx] = e;
        g_cursor [idx] = e;
    }
    if (blockIdx.x == 0 && tid == 0) g_row_ptr[N_NODES] = N_EDGES;
}

__global__ void k_fill(const int* __restrict__ src, const int* __restrict__ dst) {
    int e = blockIdx.x * blockDim.x + threadIdx.x;
    if (e < N_EDGES) {
        int d = dst[e];
        int p = atomicAdd(&g_cursor[d], 1);
        g_csr_src[p] = src[e];
    }
}

// ---------------- fp16 tensor-core GEMM (m16n8k16), fp16 out ----------------
// 128 rows x 128 cols per block, 256 threads (8 warps), W as packed half2 in smem.
__device__ __forceinline__ void mma_f16(float& c0, float& c1, float& c2, float& c3,
                                        uint32_t a0, uint32_t a1, uint32_t a2, uint32_t a3,
                                        uint32_t b0, uint32_t b1) {
    asm volatile(
        "mma.sync.aligned.m16n8k16.row.col.f32.f16.f16.f32 "
        "{%0,%1,%2,%3}, {%4,%5,%6,%7}, {%8,%9}, {%0,%1,%2,%3};"
        : "+f"(c0), "+f"(c1), "+f"(c2), "+f"(c3)
        : "r"(a0), "r"(a1), "r"(a2), "r"(a3), "r"(b0), "r"(b1));
}

#define BS_STRIDE 132
#define SMEM_GEMM (64 * BS_STRIDE * 4)   // 33792 bytes (k2-rows x packed cols)

template<bool F16SRC>
__global__ __launch_bounds__(256, 2) void k_gemm(const float* __restrict__ X32,
                                                 const float* __restrict__ W) {
    extern __shared__ uint32_t Bs[];    // [64][BS_STRIDE]; entry = {W[2k2][n], W[2k2+1][n]} fp16x2

    int tid  = threadIdx.x;
    int warp = tid >> 5;
    int lane = tid & 31;
    int row0 = blockIdx.x * 128;

    // stage + convert W (128x128 fp32 -> packed half2), b-frag friendly layout
    for (int i = tid; i < 64 * F; i += 256) {
        int k2 = i >> 7, n = i & 127;
        float w0 = W[(2 * k2    ) * F + n];
        float w1 = W[(2 * k2 + 1) * F + n];
        __half2 p = __floats2half2_rn(w0, w1);
        Bs[k2 * BS_STRIDE + (n & 7) * 16 + (n >> 3)] = *(uint32_t*)&p;
    }
    __syncthreads();

    int tig = lane & 3;          // k-pair selector
    int grp = lane >> 2;         // row/col-in-tile
    int r0 = row0 + warp * 16 + grp;
    int r1 = r0 + 8;
    bool v0 = (r0 < N_NODES), v1 = (r1 < N_NODES);
    const float*  xr0 = X32 ? X32 + (size_t)(v0 ? r0 : 0) * F : nullptr;
    const float*  xr1 = X32 ? X32 + (size_t)(v1 ? r1 : 0) * F : nullptr;
    const __half* hr0 = g_xh + (size_t)(v0 ? r0 : 0) * F;
    const __half* hr1 = g_xh + (size_t)(v1 ? r1 : 0) * F;

    float c[16][4];
#pragma unroll
    for (int nt = 0; nt < 16; nt++)
#pragma unroll
        for (int j = 0; j < 4; j++) c[nt][j] = 0.f;

#pragma unroll
    for (int kk = 0; kk < 8; kk++) {
        int k0 = kk * 16;
        uint32_t a0, a1, a2, a3;
        if (F16SRC) {
            a0 = *(const uint32_t*)&hr0[k0 + 2 * tig    ];
            a1 = *(const uint32_t*)&hr1[k0 + 2 * tig    ];
            a2 = *(const uint32_t*)&hr0[k0 + 2 * tig + 8];
            a3 = *(const uint32_t*)&hr1[k0 + 2 * tig + 8];
        } else {
            float2 f0 = *(const float2*)&xr0[k0 + 2 * tig    ];
            float2 f1 = *(const float2*)&xr1[k0 + 2 * tig    ];
            float2 f2 = *(const float2*)&xr0[k0 + 2 * tig + 8];
            float2 f3 = *(const float2*)&xr1[k0 + 2 * tig + 8];
            __half2 h0 = __floats2half2_rn(f0.x, f0.y);
            __half2 h1 = __floats2half2_rn(f1.x, f1.y);
            __half2 h2 = __floats2half2_rn(f2.x, f2.y);
            __half2 h3 = __floats2half2_rn(f3.x, f3.y);
            a0 = *(uint32_t*)&h0; a1 = *(uint32_t*)&h1;
            a2 = *(uint32_t*)&h2; a3 = *(uint32_t*)&h3;
        }

        const uint32_t* b0p = &Bs[(kk * 8 + tig    ) * BS_STRIDE + grp * 16];
        const uint32_t* b1p = &Bs[(kk * 8 + 4 + tig) * BS_STRIDE + grp * 16];
#pragma unroll
        for (int ntg = 0; ntg < 4; ntg++) {
            uint4 p0 = *(const uint4*)(b0p + ntg * 4);
            uint4 p1 = *(const uint4*)(b1p + ntg * 4);
            int nt = ntg * 4;
            mma_f16(c[nt+0][0], c[nt+0][1], c[nt+0][2], c[nt+0][3], a0,a1,a2,a3, p0.x, p1.x);
            mma_f16(c[nt+1][0], c[nt+1][1], c[nt+1][2], c[nt+1][3], a0,a1,a2,a3, p0.y, p1.y);
            mma_f16(c[nt+2][0], c[nt+2][1], c[nt+2][2], c[nt+2][3], a0,a1,a2,a3, p0.z, p1.z);
            mma_f16(c[nt+3][0], c[nt+3][1], c[nt+3][2], c[nt+3][3], a0,a1,a2,a3, p0.w, p1.w);
        }
    }

#pragma unroll
    for (int nt = 0; nt < 16; nt++) {
        int col = nt * 8 + 2 * tig;
        if (v0) *(__half2*)&g_hh[(size_t)r0 * F + col] = __floats2half2_rn(c[nt][0], c[nt][1]);
        if (v1) *(__half2*)&g_hh[(size_t)r1 * F + col] = __floats2half2_rn(c[nt][2], c[nt][3]);
    }
}

// ---------------- CSR gather: acc += iso[src]*h[src]; out = relu(acc*isi + b) ----------------
// Half-warp (16 lanes) per node; lane covers 8 features. OUT16 -> fp16 g_xh, else fp32 g_x.
template<bool OUT16>
__global__ void k_gather(const float* __restrict__ b) {
    int t = blockIdx.x * blockDim.x + threadIdx.x;
    int n = t >> 4, sub = t & 15;
    if (n >= N_NODES) return;

    int beg = g_row_ptr[n], end = g_row_ptr[n + 1];
    const uint4* hh = (const uint4*)g_hh;   // row stride = 16 uint4

    float acc[8];
#pragma unroll
    for (int d = 0; d < 8; d++) acc[d] = 0.f;

    int i = beg;
    for (; i + 4 <= end; i += 4) {
        int s0 = g_csr_src[i + 0];
        int s1 = g_csr_src[i + 1];
        int s2 = g_csr_src[i + 2];
        int s3 = g_csr_src[i + 3];
        float w0 = g_iso[s0], w1 = g_iso[s1], w2 = g_iso[s2], w3 = g_iso[s3];
        uint4 v0 = hh[s0 * 16 + sub];
        uint4 v1 = hh[s1 * 16 + sub];
        uint4 v2 = hh[s2 * 16 + sub];
        uint4 v3 = hh[s3 * 16 + sub];
#pragma unroll
        for (int q = 0; q < 4; q++) {
            uint32_t x0 = (&v0.x)[q], x1 = (&v1.x)[q], x2 = (&v2.x)[q], x3 = (&v3.x)[q];
            float2 f0 = __half22float2(*(__half2*)&x0);
            float2 f1 = __half22float2(*(__half2*)&x1);
            float2 f2 = __half22float2(*(__half2*)&x2);
            float2 f3 = __half22float2(*(__half2*)&x3);
            acc[2*q+0] = fmaf(f0.x, w0, fmaf(f1.x, w1, fmaf(f2.x, w2, fmaf(f3.x, w3, acc[2*q+0]))));
            acc[2*q+1] = fmaf(f0.y, w0, fmaf(f1.y, w1, fmaf(f2.y, w2, fmaf(f3.y, w3, acc[2*q+1]))));
        }
    }
    for (; i < end; i++) {
        int s = g_csr_src[i];
        float w = g_iso[s];
        uint4 v = hh[s * 16 + sub];
#pragma unroll
        for (int q = 0; q < 4; q++) {
            uint32_t x = (&v.x)[q];
            float2 f = __half22float2(*(__half2*)&x);
            acc[2*q+0] = fmaf(f.x, w, acc[2*q+0]);
            acc[2*q+1] = fmaf(f.y, w, acc[2*q+1]);
        }
    }

    float si = g_isi[n];
    float4 b0 = *(const float4*)&b[sub * 8];
    float4 b1 = *(const float4*)&b[sub * 8 + 4];
    float o[8];
    o[0] = fmaxf(fmaf(acc[0], si, b0.x), 0.f);
    o[1] = fmaxf(fmaf(acc[1], si, b0.y), 0.f);
    o[2] = fmaxf(fmaf(acc[2], si, b0.z), 0.f);
    o[3] = fmaxf(fmaf(acc[3], si, b0.w), 0.f);
    o[4] = fmaxf(fmaf(acc[4], si, b1.x), 0.f);
    o[5] = fmaxf(fmaf(acc[5], si, b1.y), 0.f);
    o[6] = fmaxf(fmaf(acc[6], si, b1.z), 0.f);
    o[7] = fmaxf(fmaf(acc[7], si, b1.w), 0.f);

    if (OUT16) {
        __half2 p0 = __floats2half2_rn(o[0], o[1]);
        __half2 p1 = __floats2half2_rn(o[2], o[3]);
        __half2 p2 = __floats2half2_rn(o[4], o[5]);
        __half2 p3 = __floats2half2_rn(o[6], o[7]);
        uint4 pk;
        pk.x = *(uint32_t*)&p0; pk.y = *(uint32_t*)&p1;
        pk.z = *(uint32_t*)&p2; pk.w = *(uint32_t*)&p3;
        *(uint4*)&g_xh[(size_t)n * F + sub * 8] = pk;
    } else {
        *(float4*)&g_x[(size_t)n * F + sub * 8    ] = make_float4(o[0], o[1], o[2], o[3]);
        *(float4*)&g_x[(size_t)n * F + sub * 8 + 4] = make_float4(o[4], o[5], o[6], o[7]);
    }
}

// ---------------- sum-pool exploiting sorted graph_ids ----------------
#define POOL_CHUNK 256
__global__ void k_pool(const int* __restrict__ gid, float* __restrict__ out) {
    int j = threadIdx.x;
    int n0 = blockIdx.x * POOL_CHUNK;
    int n1 = n0 + POOL_CHUNK;
    if (n1 > N_NODES) n1 = N_NODES;

    int curg = __ldg(&gid[n0]);
    float acc = 0.f;
    for (int n = n0; n < n1; n++) {
        int g = __ldg(&gid[n]);
        if (g != curg) {
            atomicAdd(&out[curg * F + j], acc);
            acc = 0.f;
            curg = g;
        }
        acc += g_x[(size_t)n * F + j];
    }
    atomicAdd(&out[curg * F + j], acc);
}

// ---------------- BN (stats fused) + MLP + log_softmax ----------------
__global__ void k_mlp(const float* __restrict__ E,
                      const float* __restrict__ gamma, const float* __restrict__ beta,
                      const float* __restrict__ fc1w, const float* __restrict__ fc1b,
                      const float* __restrict__ fc2w, const float* __restrict__ fc2b,
                      float* __restrict__ out_logits) {
    int g = blockIdx.x, j = threadIdx.x;
    __shared__ float bn[F];
    __shared__ float h[F];
    __shared__ float l[NOUT];
    __shared__ float lse;

    // per-block redundant BN stats over the [NG, F] embedding
    float s = 0.f, s2 = 0.f;
#pragma unroll 8
    for (int gg = 0; gg < NG; gg++) {
        float v = E[gg * F + j];
        s += v; s2 = fmaf(v, v, s2);
    }
    float mu = s * (1.f / NG);
    float istd = rsqrtf(s2 * (1.f / NG) - mu * mu + BN_EPS);

    bn[j] = fmaf(gamma[j] * (E[g * F + j] - mu), istd, beta[j]);
    __syncthreads();

    float acc = fc1b[j];
#pragma unroll 8
    for (int k = 0; k < F; k++) acc = fmaf(bn[k], fc1w[k * F + j], acc);
    h[j] = fmaxf(acc, 0.f);
    __syncthreads();

    if (j < NOUT) {
        float a = fc2b[j];
#pragma unroll 8
        for (int k = 0; k < F; k++) a = fmaf(h[k], fc2w[k * NOUT + j], a);
        l[j] = a;
    }
    __syncthreads();

    if (j == 0) {
        float m = -INFINITY;
        for (int o = 0; o < NOUT; o++) m = fmaxf(m, l[o]);
        float ss = 0.f;
        for (int o = 0; o < NOUT; o++) ss += expf(l[o] - m);
        lse = m + logf(ss);
    }
    __syncthreads();

    if (j < NOUT) out_logits[g * NOUT + j] = l[j] - lse;
}

// ---------------- launch ----------------
extern "C" void kernel_launch(void* const* d_in, const int* in_sizes, int n_in,
                              void* d_out, int out_size) {
    const float* n_feat = (const float*)d_in[0];
    const int*   src    = (const int*)  d_in[1];
    const int*   dst    = (const int*)  d_in[2];
    const int*   gid    = (const int*)  d_in[3];
    const float* W1     = (const float*)d_in[4];
    const float* b1     = (const float*)d_in[5];
    const float* W2     = (const float*)d_in[6];
    const float* b2     = (const float*)d_in[7];
    const float* gamma  = (const float*)d_in[8];
    const float* beta   = (const float*)d_in[9];
    const float* fc1w   = (const float*)d_in[10];
    const float* fc1b   = (const float*)d_in[11];
    const float* fc2w   = (const float*)d_in[12];
    const float* fc2b   = (const float*)d_in[13];
    float* out = (float*)d_out;

    // one-time handle setup (handles only; no device memory, no cached work)
    static cudaStream_t s_side = nullptr;
    static cudaEvent_t  evRoot = nullptr, evSide = nullptr;
    if (s_side == nullptr) {
        cudaStreamCreateWithFlags(&s_side, cudaStreamNonBlocking);
        cudaEventCreateWithFlags(&evRoot, cudaEventDisableTiming);
        cudaEventCreateWithFlags(&evSide, cudaEventDisableTiming);
    }

    const int TB = 256;
    const int nodeBlocks   = (N_NODES + TB - 1) / TB;
    const int edgeBlocks   = (N_EDGES + TB - 1) / TB;
    const int gatherBlocks = (N_NODES * 16 + TB - 1) / TB;
    const int poolBlocks   = (N_NODES + POOL_CHUNK - 1) / POOL_CHUNK;
    const int gemmBlocks   = (N_NODES + 127) / 128;

    // independent of everything else: zero embedding output early
    cudaMemsetAsync(out, 0, NG * F * sizeof(float), 0);

    // fork: GEMM-1 runs beside the CSR build
    cudaEventRecord(evRoot, 0);
    cudaStreamWaitEvent(s_side, evRoot, 0);
    k_gemm<false><<<gemmBlocks, 256, SMEM_GEMM, s_side>>>(n_feat, W1);
    cudaEventRecord(evSide, s_side);

    // CSR build on main stream
    k_zero_deg<<<nodeBlocks, TB>>>();
    k_deg<<<edgeBlocks, TB>>>(src, dst);
    k_scan1<<<SCAN_NB, SCAN_B>>>();
    k_scan3<<<SCAN_NB, SCAN_B>>>();
    k_fill<<<edgeBlocks, TB>>>(src, dst);

    // join, then layer 1 aggregate (emits fp16 for GEMM-2)
    cudaStreamWaitEvent(0, evSide, 0);
    k_gather<true><<<gatherBlocks, TB>>>(b1);

    // layer 2
    k_gemm<true><<<gemmBlocks, 256, SMEM_GEMM>>>(nullptr, W2);
    k_gather<false><<<gatherBlocks, TB>>>(b2);

    // pooling + head
    k_pool<<<poolBlocks, F>>>(gid, out);
    k_mlp<<<NG, F>>>(out, gamma, beta, fc1w, fc1b, fc2w, fc2b, out + NG * F);
}